// round 9
// baseline (speedup 1.0000x reference)
#include <cuda_runtime.h>
#include <cuda_bf16.h>
#include <cstdint>

// Problem constants
#define EE   512
#define HH   8
#define BBSZ 32
#define PPN  512
#define SSN  1024
#define MQ   (BBSZ * PPN)    // 16384
#define MKV  (BBSZ * SSN)    // 32768

typedef __nv_bfloat16 bf16;

// ---------------------------------------------------------------------------
// Scratch (device globals; no allocation allowed)
// ---------------------------------------------------------------------------
__device__ __align__(16) bf16 g_qa_hi[MQ * EE],  g_qa_lo[MQ * EE];
__device__ __align__(16) bf16 g_ka_hi[MKV * EE], g_ka_lo[MKV * EE];
__device__ __align__(16) bf16 g_va_hi[MKV * EE], g_va_lo[MKV * EE];
__device__ __align__(16) bf16 g_Qh[MQ * EE],  g_Ql[MQ * EE];
__device__ __align__(16) bf16 g_Kh[MKV * EE], g_Kl[MKV * EE];
__device__ __align__(16) bf16 g_Vh[MKV * EE], g_Vl[MKV * EE];
__device__ __align__(16) bf16 g_Ch[MQ * EE],  g_Cl[MQ * EE];
__device__ __align__(16) bf16 g_w_hi[4][EE * EE], g_w_lo[4][EE * EE];
__device__ __align__(16) unsigned char g_mskb[(size_t)BBSZ * PPN * SSN / 8];

// ---------------------------------------------------------------------------
// Small helpers
// ---------------------------------------------------------------------------
__device__ __forceinline__ uint32_t smem_u32(const void* p) {
    uint32_t a;
    asm("{ .reg .u64 t; cvta.to.shared.u64 t, %1; cvt.u32.u64 %0, t; }"
        : "=r"(a) : "l"(p));
    return a;
}
__device__ __forceinline__ void ldsm_x4(uint32_t& r0, uint32_t& r1,
                                        uint32_t& r2, uint32_t& r3, uint32_t a) {
    asm volatile("ldmatrix.sync.aligned.m8n8.x4.shared.b16 {%0,%1,%2,%3}, [%4];"
                 : "=r"(r0), "=r"(r1), "=r"(r2), "=r"(r3) : "r"(a));
}
__device__ __forceinline__ void ldsm_x4_t(uint32_t& r0, uint32_t& r1,
                                          uint32_t& r2, uint32_t& r3, uint32_t a) {
    asm volatile("ldmatrix.sync.aligned.m8n8.x4.trans.shared.b16 {%0,%1,%2,%3}, [%4];"
                 : "=r"(r0), "=r"(r1), "=r"(r2), "=r"(r3) : "r"(a));
}
__device__ __forceinline__ void mma_bf16(float* c, const uint32_t* a,
                                         uint32_t b0, uint32_t b1) {
    asm volatile(
        "mma.sync.aligned.m16n8k16.row.col.f32.bf16.bf16.f32 "
        "{%0,%1,%2,%3}, {%4,%5,%6,%7}, {%8,%9}, {%0,%1,%2,%3};"
        : "+f"(c[0]), "+f"(c[1]), "+f"(c[2]), "+f"(c[3])
        : "r"(a[0]), "r"(a[1]), "r"(a[2]), "r"(a[3]), "r"(b0), "r"(b1));
}
__device__ __forceinline__ void cp16(uint32_t dst, const void* src) {
    asm volatile("cp.async.cg.shared.global [%0], [%1], 16;"
                 :: "r"(dst), "l"(src) : "memory");
}
__device__ __forceinline__ void cp8(uint32_t dst, const void* src) {
    asm volatile("cp.async.ca.shared.global [%0], [%1], 8;"
                 :: "r"(dst), "l"(src) : "memory");
}
__device__ __forceinline__ void split2(float a, float b, uint32_t& h, uint32_t& l) {
    __nv_bfloat162 H, L;
    H.x = __float2bfloat16(a);
    H.y = __float2bfloat16(b);
    L.x = __float2bfloat16(a - __bfloat162float(H.x));
    L.y = __float2bfloat16(b - __bfloat162float(H.y));
    h = *reinterpret_cast<uint32_t*>(&H);
    l = *reinterpret_cast<uint32_t*>(&L);
}

// ---------------------------------------------------------------------------
// fp32 -> bf16 hi/lo split (vectorized x4)
// ---------------------------------------------------------------------------
__global__ void convert_split(const float* __restrict__ X,
                              bf16* __restrict__ H, bf16* __restrict__ L, int n4)
{
    int i = blockIdx.x * blockDim.x + threadIdx.x;
    if (i >= n4) return;
    float4 x = ((const float4*)X)[i];
    uint32_t h0, l0, h1, l1;
    split2(x.x, x.y, h0, l0);
    split2(x.z, x.w, h1, l1);
    ((uint32_t*)H)[2 * i] = h0; ((uint32_t*)H)[2 * i + 1] = h1;
    ((uint32_t*)L)[2 * i] = l0; ((uint32_t*)L)[2 * i + 1] = l1;
}

// all four weights in one launch (grid.y selects weight)
__global__ void convert_split_w(const float* __restrict__ w0,
                                const float* __restrict__ w1,
                                const float* __restrict__ w2,
                                const float* __restrict__ w3,
                                bf16* __restrict__ H, bf16* __restrict__ L, int n4)
{
    const float* src = (blockIdx.y == 0) ? w0 : (blockIdx.y == 1) ? w1
                     : (blockIdx.y == 2) ? w2 : w3;
    int i = blockIdx.x * blockDim.x + threadIdx.x;
    if (i >= n4) return;
    size_t o = (size_t)blockIdx.y * n4 + i;
    float4 x = ((const float4*)src)[i];
    uint32_t h0, l0, h1, l1;
    split2(x.x, x.y, h0, l0);
    split2(x.z, x.w, h1, l1);
    ((uint32_t*)H)[2 * o] = h0; ((uint32_t*)H)[2 * o + 1] = h1;
    ((uint32_t*)L)[2 * o] = l0; ((uint32_t*)L)[2 * o + 1] = l1;
}

// mask int32 -> bitmask (1 bit per element, little-endian within bytes)
__global__ void pack_mask_bits(const int* __restrict__ m,
                               unsigned int* __restrict__ o, int n32)
{
    int i = blockIdx.x * blockDim.x + threadIdx.x;
    if (i >= n32) return;
    const int4* s = (const int4*)m + (size_t)i * 8;
    unsigned int v = 0;
#pragma unroll
    for (int q = 0; q < 8; q++) {
        int4 a = s[q];
        v |= (((unsigned)a.x & 1u) | (((unsigned)a.y & 1u) << 1) |
              (((unsigned)a.z & 1u) << 2) | (((unsigned)a.w & 1u) << 3)) << (q * 4);
    }
    o[i] = v;
}

// ---------------------------------------------------------------------------
// Fused tensor-core GEMM: C[M,512] = A[M,512] @ W[512,512]^T
// fp32 via bf16 3-term split. Paired hi|lo smem rows (128B = hi64|lo64),
// K-chunk 32 (2 k16 steps, 3 terms each). 3-stage ring, 1 sync per chunk.
// mode 0: fused Q/K/V projections (grid.y: 0..127 Q, 128..383 K, 384..639 V),
//         bf16 hi/lo split output.
// mode 1: O-projection from g_Ch/g_Cl, fp32 + bias output.
// ---------------------------------------------------------------------------
#define GSM (3 * 32768)

__global__ __launch_bounds__(256, 2) void gemm_fused(
    int mode, const float* __restrict__ bias, float* __restrict__ outF)
{
    extern __shared__ char smem[];
    const uint32_t sb = smem_u32(smem);
    const int tid = threadIdx.x;
    const int wid = tid >> 5;
    const int lane = tid & 31;
    const int wm = wid >> 2;
    const int wn = wid & 3;

    const bf16 *Ahi, *Alo, *Whi, *Wlo;
    bf16 *Ch = nullptr, *Cl = nullptr;
    float* Cf = nullptr;
    int my;
    if (mode) {
        Ahi = g_Ch; Alo = g_Cl; Whi = g_w_hi[3]; Wlo = g_w_lo[3];
        Cf = outF; my = blockIdx.y;
    } else {
        int y = blockIdx.y;
        if (y < 128)      { Ahi = g_qa_hi; Alo = g_qa_lo; Whi = g_w_hi[0]; Wlo = g_w_lo[0];
                            Ch = g_Qh; Cl = g_Ql; my = y; }
        else if (y < 384) { Ahi = g_ka_hi; Alo = g_ka_lo; Whi = g_w_hi[1]; Wlo = g_w_lo[1];
                            Ch = g_Kh; Cl = g_Kl; my = y - 128; }
        else              { Ahi = g_va_hi; Alo = g_va_lo; Whi = g_w_hi[2]; Wlo = g_w_lo[2];
                            Ch = g_Vh; Cl = g_Vl; my = y - 384; }
    }
    const int m0 = my * 128;
    const int n0 = blockIdx.x * 128;

    // loads: thread covers 64B (hi or lo half) of one 128B row
    const int r = tid >> 1;
    const int half = tid & 1;
    uint32_t so[4];
#pragma unroll
    for (int i = 0; i < 4; i++) {
        uint32_t bo = (uint32_t)r * 128 + half * 64 + i * 16;
        so[i] = bo ^ ((bo >> 3) & 0x70);
    }
    const bf16* Asrc = half ? Alo : Ahi;
    const bf16* Wsrc = half ? Wlo : Whi;

    const int lrow = lane & 15;
    const uint32_t kxor = (uint32_t)(lane & 7) << 4;
    const uint32_t khalf = (uint32_t)(lane >> 4) * 16;

    float acc[4][4][4];
#pragma unroll
    for (int i = 0; i < 4; i++)
#pragma unroll
        for (int f = 0; f < 4; f++)
#pragma unroll
            for (int c = 0; c < 4; c++) acc[i][f][c] = 0.f;

    auto issue = [&](int kc, int buf) {
        const char* ag = (const char*)(Asrc + (size_t)(m0 + r) * 512 + kc * 32);
        const char* bg = (const char*)(Wsrc + (size_t)(n0 + r) * 512 + kc * 32);
        uint32_t ab = sb + (uint32_t)buf * 32768;
        uint32_t bb = ab + 16384;
#pragma unroll
        for (int i = 0; i < 4; i++) {
            cp16(ab + so[i], ag + i * 16);
            cp16(bb + so[i], bg + i * 16);
        }
        asm volatile("cp.async.commit_group;" ::: "memory");
    };

    issue(0, 0);
    issue(1, 1);

    for (int kc = 0; kc < 16; kc++) {
        if (kc == 15) asm volatile("cp.async.wait_group 0;" ::: "memory");
        else          asm volatile("cp.async.wait_group 1;" ::: "memory");
        __syncthreads();
        if (kc + 2 < 16) issue(kc + 2, (kc + 2) % 3);

        const uint32_t ab = sb + (uint32_t)(kc % 3) * 32768;
        const uint32_t bb = ab + 16384;
#pragma unroll
        for (int s = 0; s < 2; s++) {
            const uint32_t khi = ((uint32_t)(s * 32) + khalf) ^ kxor;
            const uint32_t klo = ((uint32_t)(64 + s * 32) + khalf) ^ kxor;
            uint32_t af[4][4], bh[2][4], bl[2][4];
#pragma unroll
            for (int im = 0; im < 4; im++)
                ldsm_x4(af[im][0], af[im][1], af[im][2], af[im][3],
                        ab + (uint32_t)(wm * 64 + im * 16 + lrow) * 128 + khi);
#pragma unroll
            for (int nb = 0; nb < 2; nb++) {
                uint32_t rowa = bb + (uint32_t)(wn * 32 + nb * 16 + lrow) * 128;
                ldsm_x4(bh[nb][0], bh[nb][1], bh[nb][2], bh[nb][3], rowa + khi);
                ldsm_x4(bl[nb][0], bl[nb][1], bl[nb][2], bl[nb][3], rowa + klo);
            }
            // ah x Wh, ah x Wl
#pragma unroll
            for (int im = 0; im < 4; im++)
#pragma unroll
                for (int f = 0; f < 4; f++) {
                    mma_bf16(acc[im][f], af[im],
                             bh[f >> 1][f & 1], bh[f >> 1][(f & 1) + 2]);
                    mma_bf16(acc[im][f], af[im],
                             bl[f >> 1][f & 1], bl[f >> 1][(f & 1) + 2]);
                }
            // reload al into af, then al x Wh
#pragma unroll
            for (int im = 0; im < 4; im++)
                ldsm_x4(af[im][0], af[im][1], af[im][2], af[im][3],
                        ab + (uint32_t)(wm * 64 + im * 16 + lrow) * 128 + klo);
#pragma unroll
            for (int im = 0; im < 4; im++)
#pragma unroll
                for (int f = 0; f < 4; f++)
                    mma_bf16(acc[im][f], af[im],
                             bh[f >> 1][f & 1], bh[f >> 1][(f & 1) + 2]);
        }
    }

    const int crow = lane >> 2;
    const int ccol = (lane & 3) * 2;
#pragma unroll
    for (int im = 0; im < 4; im++) {
#pragma unroll
        for (int f = 0; f < 4; f++) {
            int row = m0 + wm * 64 + im * 16 + crow;
            int col = n0 + wn * 32 + (f >> 1) * 16 + (f & 1) * 8 + ccol;
            if (Cf) {
                float b0 = bias ? bias[col] : 0.f;
                float b1 = bias ? bias[col + 1] : 0.f;
                float2 v0 = {acc[im][f][0] + b0, acc[im][f][1] + b1};
                float2 v1 = {acc[im][f][2] + b0, acc[im][f][3] + b1};
                *(float2*)&Cf[(size_t)row * 512 + col] = v0;
                *(float2*)&Cf[(size_t)(row + 8) * 512 + col] = v1;
            } else {
                uint32_t hp, lp;
                split2(acc[im][f][0], acc[im][f][1], hp, lp);
                *(uint32_t*)&Ch[(size_t)row * 512 + col] = hp;
                *(uint32_t*)&Cl[(size_t)row * 512 + col] = lp;
                split2(acc[im][f][2], acc[im][f][3], hp, lp);
                *(uint32_t*)&Ch[(size_t)(row + 8) * 512 + col] = hp;
                *(uint32_t*)&Cl[(size_t)(row + 8) * 512 + col] = lp;
            }
        }
    }
}

// ---------------------------------------------------------------------------
// Tensor-core flash attention. CTA: 128 q-rows x one (b,h); 8 warps;
// S-tiles of 64; double-buffered KV + bitmask; 1 sync per tile; 2 CTAs/SM.
// ---------------------------------------------------------------------------
#define ATT_BUF 33792                    // Kh 8K | Kl 8K | Vh 8K | Vl 8K | mask 1K
#define ATT_SM  (32768 + 2 * ATT_BUF)    // + Q hi/lo 32K  = 100352

__global__ __launch_bounds__(256, 2) void flash_tc()
{
    extern __shared__ char smem[];
    const uint32_t sb = smem_u32(smem);
    const int tid = threadIdx.x;
    const int wid = tid >> 5;
    const int lane = tid & 31;
    const int b = blockIdx.y >> 3;
    const int hd = blockIdx.y & 7;
    const int p0 = blockIdx.x * 128;

    const int lrow = lane & 15;
    const uint32_t kxor = (uint32_t)(lane & 7) << 4;
    const uint32_t khalf = (uint32_t)(lane >> 4) * 16;

    // ---- Q load (once; joins tile-0's commit group) ----
    const int qr = tid >> 1;
    const int qhalf = tid & 1;
    {
        const char* sq_h = (const char*)(g_Qh + (size_t)(b * PPN + p0 + qr) * 512 + hd * 64)
                           + qhalf * 64;
        const char* sq_l = (const char*)(g_Ql + (size_t)(b * PPN + p0 + qr) * 512 + hd * 64)
                           + qhalf * 64;
#pragma unroll
        for (int i = 0; i < 4; i++) {
            uint32_t bo = (uint32_t)qr * 128 + qhalf * 64 + i * 16;
            uint32_t sw = bo ^ ((bo >> 3) & 0x70);
            cp16(sb + sw, sq_h + i * 16);
            cp16(sb + 16384 + sw, sq_l + i * 16);
        }
    }

    // ---- K/V tile addressing ----
    const int kvr = tid >> 2;
    const int kvq = tid & 3;
    uint32_t kvsw0, kvsw1;
    {
        uint32_t bo0 = (uint32_t)kvr * 128 + kvq * 32;
        uint32_t bo1 = bo0 + 16;
        kvsw0 = bo0 ^ ((bo0 >> 3) & 0x70);
        kvsw1 = bo1 ^ ((bo1 >> 3) & 0x70);
    }

    auto issue_tile = [&](int t) {
        const uint32_t bufo = sb + 32768 + (uint32_t)(t & 1) * ATT_BUF;
        const int s0 = t * 64;
        const size_t kvrow = (size_t)(b * SSN + s0 + kvr) * 512 + hd * 64;
        const char* srcKh = (const char*)(g_Kh + kvrow) + kvq * 32;
        const char* srcKl = (const char*)(g_Kl + kvrow) + kvq * 32;
        const char* srcVh = (const char*)(g_Vh + kvrow) + kvq * 32;
        const char* srcVl = (const char*)(g_Vl + kvrow) + kvq * 32;
        cp16(bufo + kvsw0, srcKh);          cp16(bufo + kvsw1, srcKh + 16);
        cp16(bufo + 8192 + kvsw0, srcKl);   cp16(bufo + 8192 + kvsw1, srcKl + 16);
        cp16(bufo + 16384 + kvsw0, srcVh);  cp16(bufo + 16384 + kvsw1, srcVh + 16);
        cp16(bufo + 24576 + kvsw0, srcVl);  cp16(bufo + 24576 + kvsw1, srcVl + 16);
        if (tid < 128) {
            const unsigned char* srcM =
                g_mskb + (size_t)(b * PPN + p0 + tid) * (SSN / 8) + t * 8;
            cp8(bufo + 32768 + (uint32_t)tid * 8, srcM);
        }
        asm volatile("cp.async.commit_group;" ::: "memory");
    };

    issue_tile(0);

    float m0 = -1e30f, m1 = -1e30f, l0 = 0.f, l1 = 0.f;
    float oacc[8][4];
#pragma unroll
    for (int d = 0; d < 8; d++)
#pragma unroll
        for (int c = 0; c < 4; c++) oacc[d][c] = 0.f;

    const int r0 = lane >> 2;
    const int mcol = (lane & 3) * 2;

    for (int t = 0; t < 16; t++) {
        asm volatile("cp.async.wait_group 0;" ::: "memory");
        __syncthreads();
        if (t < 15) issue_tile(t + 1);

        const uint32_t bufo = sb + 32768 + (uint32_t)(t & 1) * ATT_BUF;
        const uint32_t Khb = bufo, Klb = bufo + 8192;
        const uint32_t Vhb = bufo + 16384, Vlb = bufo + 24576;
        const char* mskp = smem + (bufo - sb) + 32768;

        // ---- scores ----
        float sacc[8][4];
#pragma unroll
        for (int n = 0; n < 8; n++)
#pragma unroll
            for (int c = 0; c < 4; c++) sacc[n][c] = 0.f;

#pragma unroll
        for (int kc = 0; kc < 4; kc++) {
            const uint32_t kpart = ((uint32_t)(kc * 32) + khalf) ^ kxor;
            uint32_t ah[4], al[4];
            ldsm_x4(ah[0], ah[1], ah[2], ah[3],
                    sb + (uint32_t)(wid * 16 + lrow) * 128 + kpart);
            ldsm_x4(al[0], al[1], al[2], al[3],
                    sb + 16384 + (uint32_t)(wid * 16 + lrow) * 128 + kpart);
#pragma unroll
            for (int ng = 0; ng < 4; ng++) {
                uint32_t kh[4], kl[4];
                ldsm_x4(kh[0], kh[1], kh[2], kh[3],
                        Khb + (uint32_t)(ng * 16 + lrow) * 128 + kpart);
                ldsm_x4(kl[0], kl[1], kl[2], kl[3],
                        Klb + (uint32_t)(ng * 16 + lrow) * 128 + kpart);
                mma_bf16(sacc[2 * ng], ah, kh[0], kh[2]);
                mma_bf16(sacc[2 * ng], ah, kl[0], kl[2]);
                mma_bf16(sacc[2 * ng], al, kh[0], kh[2]);
                mma_bf16(sacc[2 * ng + 1], ah, kh[1], kh[3]);
                mma_bf16(sacc[2 * ng + 1], ah, kl[1], kl[3]);
                mma_bf16(sacc[2 * ng + 1], al, kh[1], kh[3]);
            }
        }

        // ---- bitmask + online softmax ----
        const float scale = 0.125f;
        const uint64_t mA = *(const uint64_t*)(mskp + (wid * 16 + r0) * 8);
        const uint64_t mB = *(const uint64_t*)(mskp + (wid * 16 + r0 + 8) * 8);
        float mx0 = -1e30f, mx1 = -1e30f;
#pragma unroll
        for (int nb = 0; nb < 8; nb++) {
            const int sh = nb * 8 + mcol;
            float* s = sacc[nb];
            s[0] = ((mA >> sh) & 1)       ? -1e30f : s[0] * scale;
            s[1] = ((mA >> (sh + 1)) & 1) ? -1e30f : s[1] * scale;
            s[2] = ((mB >> sh) & 1)       ? -1e30f : s[2] * scale;
            s[3] = ((mB >> (sh + 1)) & 1) ? -1e30f : s[3] * scale;
            mx0 = fmaxf(mx0, fmaxf(s[0], s[1]));
            mx1 = fmaxf(mx1, fmaxf(s[2], s[3]));
        }
        mx0 = fmaxf(mx0, __shfl_xor_sync(0xffffffffu, mx0, 1));
        mx0 = fmaxf(mx0, __shfl_xor_sync(0xffffffffu, mx0, 2));
        mx1 = fmaxf(mx1, __shfl_xor_sync(0xffffffffu, mx1, 1));
        mx1 = fmaxf(mx1, __shfl_xor_sync(0xffffffffu, mx1, 2));
        float mn0 = fmaxf(m0, mx0), mn1 = fmaxf(m1, mx1);
        float f0 = __expf(m0 - mn0), f1 = __expf(m1 - mn1);
        m0 = mn0; m1 = mn1;
        float sum0 = 0.f, sum1 = 0.f;
#pragma unroll
        for (int nb = 0; nb < 8; nb++) {
            float* s = sacc[nb];
            s[0] = __expf(s[0] - mn0); s[1] = __expf(s[1] - mn0);
            s[2] = __expf(s[2] - mn1); s[3] = __expf(s[3] - mn1);
            sum0 += s[0] + s[1];
            sum1 += s[2] + s[3];
        }
        sum0 += __shfl_xor_sync(0xffffffffu, sum0, 1);
        sum0 += __shfl_xor_sync(0xffffffffu, sum0, 2);
        sum1 += __shfl_xor_sync(0xffffffffu, sum1, 1);
        sum1 += __shfl_xor_sync(0xffffffffu, sum1, 2);
        l0 = f0 * l0 + sum0;
        l1 = f1 * l1 + sum1;
#pragma unroll
        for (int d = 0; d < 8; d++) {
            oacc[d][0] *= f0; oacc[d][1] *= f0;
            oacc[d][2] *= f1; oacc[d][3] *= f1;
        }

        // ---- P @ V (P hi/lo packed per kc) ----
#pragma unroll
        for (int kc = 0; kc < 4; kc++) {
            uint32_t ph[4], pl[4];
            float* pe = sacc[2 * kc];
            float* po = sacc[2 * kc + 1];
            split2(pe[0], pe[1], ph[0], pl[0]);
            split2(pe[2], pe[3], ph[1], pl[1]);
            split2(po[0], po[1], ph[2], pl[2]);
            split2(po[2], po[3], ph[3], pl[3]);
            const uint32_t srow = (uint32_t)(kc * 16 + lrow) * 128;
#pragma unroll
            for (int db = 0; db < 4; db++) {
                const uint32_t dpart = ((uint32_t)(db * 32) + khalf) ^ kxor;
                uint32_t vh[4], vl[4];
                ldsm_x4_t(vh[0], vh[1], vh[2], vh[3], Vhb + srow + dpart);
                ldsm_x4_t(vl[0], vl[1], vl[2], vl[3], Vlb + srow + dpart);
                mma_bf16(oacc[2 * db], ph, vh[0], vh[1]);
                mma_bf16(oacc[2 * db], ph, vl[0], vl[1]);
                mma_bf16(oacc[2 * db], pl, vh[0], vh[1]);
                mma_bf16(oacc[2 * db + 1], ph, vh[2], vh[3]);
                mma_bf16(oacc[2 * db + 1], ph, vl[2], vl[3]);
                mma_bf16(oacc[2 * db + 1], pl, vh[2], vh[3]);
            }
        }
    }

    // ---- epilogue: normalize, split, store ctx ----
    const float inv0 = 1.f / l0;
    const float inv1 = 1.f / l1;
    const size_t rowA = (size_t)(b * PPN + p0 + wid * 16 + r0) * 512 + hd * 64;
    const size_t rowB = rowA + (size_t)8 * 512;
#pragma unroll
    for (int d = 0; d < 8; d++) {
        uint32_t hp, lp;
        split2(oacc[d][0] * inv0, oacc[d][1] * inv0, hp, lp);
        *(uint32_t*)&g_Ch[rowA + d * 8 + mcol] = hp;
        *(uint32_t*)&g_Cl[rowA + d * 8 + mcol] = lp;
        split2(oacc[d][2] * inv1, oacc[d][3] * inv1, hp, lp);
        *(uint32_t*)&g_Ch[rowB + d * 8 + mcol] = hp;
        *(uint32_t*)&g_Cl[rowB + d * 8 + mcol] = lp;
    }
}

// ---------------------------------------------------------------------------
extern "C" void kernel_launch(void* const* d_in, const int* in_sizes, int n_in,
                              void* d_out, int out_size)
{
    const float* query = (const float*)d_in[0];
    const float* key   = (const float*)d_in[1];
    const float* value = (const float*)d_in[2];
    const int*   mask  = (const int*)d_in[3];
    const float* W0 = (const float*)d_in[4];
    const float* W1 = (const float*)d_in[5];
    const float* W2 = (const float*)d_in[6];
    const float* W3 = (const float*)d_in[7];
    const float* bo = (const float*)d_in[8];
    float* out = (float*)d_out;

    bf16 *qah, *qal, *kah, *kal, *vah, *val, *wh, *wl;
    unsigned int* mkb;
    cudaGetSymbolAddress((void**)&qah, g_qa_hi);
    cudaGetSymbolAddress((void**)&qal, g_qa_lo);
    cudaGetSymbolAddress((void**)&kah, g_ka_hi);
    cudaGetSymbolAddress((void**)&kal, g_ka_lo);
    cudaGetSymbolAddress((void**)&vah, g_va_hi);
    cudaGetSymbolAddress((void**)&val, g_va_lo);
    cudaGetSymbolAddress((void**)&wh, g_w_hi);
    cudaGetSymbolAddress((void**)&wl, g_w_lo);
    cudaGetSymbolAddress((void**)&mkb, g_mskb);

    cudaFuncSetAttribute(gemm_fused, cudaFuncAttributeMaxDynamicSharedMemorySize, GSM);
    cudaFuncSetAttribute(flash_tc, cudaFuncAttributeMaxDynamicSharedMemorySize, ATT_SM);

    dim3 blk(256);

    pack_mask_bits<<<(BBSZ * PPN * SSN / 32 + 255) / 256, 256>>>(
        mask, mkb, BBSZ * PPN * SSN / 32);
    convert_split_w<<<dim3(EE * EE / 4 / 256, 4), 256>>>(
        W0, W1, W2, W3, wh, wl, EE * EE / 4);
    convert_split<<<(MQ * EE / 4 + 255) / 256, 256>>>(query, qah, qal, MQ * EE / 4);
    convert_split<<<(MKV * EE / 4 + 255) / 256, 256>>>(key, kah, kal, MKV * EE / 4);
    convert_split<<<(MKV * EE / 4 + 255) / 256, 256>>>(value, vah, val, MKV * EE / 4);

    gemm_fused<<<dim3(4, 640), blk, GSM>>>(0, nullptr, nullptr);

    flash_tc<<<dim3(PPN / 128, BBSZ * HH), blk, ATT_SM>>>();

    gemm_fused<<<dim3(4, 128), blk, GSM>>>(1, bo, out);
}

// round 10
// speedup vs baseline: 1.0023x; 1.0023x over previous
#include <cuda_runtime.h>
#include <cuda_bf16.h>
#include <cstdint>

// Problem constants
#define EE   512
#define HH   8
#define BBSZ 32
#define PPN  512
#define SSN  1024
#define MQ   (BBSZ * PPN)    // 16384
#define MKV  (BBSZ * SSN)    // 32768

typedef __nv_bfloat16 bf16;

// ---------------------------------------------------------------------------
// Scratch (device globals; no allocation allowed)
// ---------------------------------------------------------------------------
__device__ __align__(16) bf16 g_qa_hi[MQ * EE],  g_qa_lo[MQ * EE];
__device__ __align__(16) bf16 g_ka_hi[MKV * EE], g_ka_lo[MKV * EE];
__device__ __align__(16) bf16 g_va_hi[MKV * EE], g_va_lo[MKV * EE];
__device__ __align__(16) bf16 g_Qh[MQ * EE],  g_Ql[MQ * EE];
__device__ __align__(16) bf16 g_Kh[MKV * EE], g_Kl[MKV * EE];
__device__ __align__(16) bf16 g_Vh[MKV * EE], g_Vl[MKV * EE];
__device__ __align__(16) bf16 g_Ch[MQ * EE],  g_Cl[MQ * EE];
__device__ __align__(16) bf16 g_w_hi[4][EE * EE], g_w_lo[4][EE * EE];
__device__ __align__(16) unsigned char g_mskb[(size_t)BBSZ * PPN * SSN / 8];

// ---------------------------------------------------------------------------
// Small helpers
// ---------------------------------------------------------------------------
__device__ __forceinline__ uint32_t smem_u32(const void* p) {
    uint32_t a;
    asm("{ .reg .u64 t; cvta.to.shared.u64 t, %1; cvt.u32.u64 %0, t; }"
        : "=r"(a) : "l"(p));
    return a;
}
__device__ __forceinline__ void ldsm_x4(uint32_t& r0, uint32_t& r1,
                                        uint32_t& r2, uint32_t& r3, uint32_t a) {
    asm volatile("ldmatrix.sync.aligned.m8n8.x4.shared.b16 {%0,%1,%2,%3}, [%4];"
                 : "=r"(r0), "=r"(r1), "=r"(r2), "=r"(r3) : "r"(a));
}
__device__ __forceinline__ void ldsm_x4_t(uint32_t& r0, uint32_t& r1,
                                          uint32_t& r2, uint32_t& r3, uint32_t a) {
    asm volatile("ldmatrix.sync.aligned.m8n8.x4.trans.shared.b16 {%0,%1,%2,%3}, [%4];"
                 : "=r"(r0), "=r"(r1), "=r"(r2), "=r"(r3) : "r"(a));
}
__device__ __forceinline__ void mma_bf16(float* c, const uint32_t* a,
                                         uint32_t b0, uint32_t b1) {
    asm volatile(
        "mma.sync.aligned.m16n8k16.row.col.f32.bf16.bf16.f32 "
        "{%0,%1,%2,%3}, {%4,%5,%6,%7}, {%8,%9}, {%0,%1,%2,%3};"
        : "+f"(c[0]), "+f"(c[1]), "+f"(c[2]), "+f"(c[3])
        : "r"(a[0]), "r"(a[1]), "r"(a[2]), "r"(a[3]), "r"(b0), "r"(b1));
}
__device__ __forceinline__ void cp16(uint32_t dst, const void* src) {
    asm volatile("cp.async.cg.shared.global [%0], [%1], 16;"
                 :: "r"(dst), "l"(src) : "memory");
}
__device__ __forceinline__ void cp8(uint32_t dst, const void* src) {
    asm volatile("cp.async.ca.shared.global [%0], [%1], 8;"
                 :: "r"(dst), "l"(src) : "memory");
}
__device__ __forceinline__ void split2(float a, float b, uint32_t& h, uint32_t& l) {
    __nv_bfloat162 H, L;
    H.x = __float2bfloat16(a);
    H.y = __float2bfloat16(b);
    L.x = __float2bfloat16(a - __bfloat162float(H.x));
    L.y = __float2bfloat16(b - __bfloat162float(H.y));
    h = *reinterpret_cast<uint32_t*>(&H);
    l = *reinterpret_cast<uint32_t*>(&L);
}

// ---------------------------------------------------------------------------
// fp32 -> bf16 hi/lo split, Q+K+V in one launch (region by flat index)
// ---------------------------------------------------------------------------
#define N4Q (MQ * EE / 4)
#define N4K (MKV * EE / 4)

__global__ void convert_qkv(const float* __restrict__ q,
                            const float* __restrict__ k,
                            const float* __restrict__ v)
{
    int i = blockIdx.x * blockDim.x + threadIdx.x;
    const float* src;
    bf16 *H, *L;
    int j = i;
    if (i < N4Q) { src = q; H = g_qa_hi; L = g_qa_lo; }
    else if (i < N4Q + N4K) { src = k; H = g_ka_hi; L = g_ka_lo; j = i - N4Q; }
    else if (i < N4Q + 2 * N4K) { src = v; H = g_va_hi; L = g_va_lo; j = i - N4Q - N4K; }
    else return;
    float4 x = ((const float4*)src)[j];
    uint32_t h0, l0, h1, l1;
    split2(x.x, x.y, h0, l0);
    split2(x.z, x.w, h1, l1);
    ((uint32_t*)H)[2 * j] = h0; ((uint32_t*)H)[2 * j + 1] = h1;
    ((uint32_t*)L)[2 * j] = l0; ((uint32_t*)L)[2 * j + 1] = l1;
}

// all four weights in one launch (grid.y selects weight)
__global__ void convert_split_w(const float* __restrict__ w0,
                                const float* __restrict__ w1,
                                const float* __restrict__ w2,
                                const float* __restrict__ w3,
                                bf16* __restrict__ H, bf16* __restrict__ L, int n4)
{
    const float* src = (blockIdx.y == 0) ? w0 : (blockIdx.y == 1) ? w1
                     : (blockIdx.y == 2) ? w2 : w3;
    int i = blockIdx.x * blockDim.x + threadIdx.x;
    if (i >= n4) return;
    size_t o = (size_t)blockIdx.y * n4 + i;
    float4 x = ((const float4*)src)[i];
    uint32_t h0, l0, h1, l1;
    split2(x.x, x.y, h0, l0);
    split2(x.z, x.w, h1, l1);
    ((uint32_t*)H)[2 * o] = h0; ((uint32_t*)H)[2 * o + 1] = h1;
    ((uint32_t*)L)[2 * o] = l0; ((uint32_t*)L)[2 * o + 1] = l1;
}

// mask int32 -> bitmask (1 bit per element)
__global__ void pack_mask_bits(const int* __restrict__ m,
                               unsigned int* __restrict__ o, int n32)
{
    int i = blockIdx.x * blockDim.x + threadIdx.x;
    if (i >= n32) return;
    const int4* s = (const int4*)m + (size_t)i * 8;
    unsigned int v = 0;
#pragma unroll
    for (int q = 0; q < 8; q++) {
        int4 a = s[q];
        v |= (((unsigned)a.x & 1u) | (((unsigned)a.y & 1u) << 1) |
              (((unsigned)a.z & 1u) << 2) | (((unsigned)a.w & 1u) << 3)) << (q * 4);
    }
    o[i] = v;
}

// ---------------------------------------------------------------------------
// Fused tensor-core GEMM: C[M,512] = A[M,512] @ W[512,512]^T
// fp32 via bf16 3-term split. Paired hi|lo smem rows (128B = hi64|lo64),
// K-chunk 32. 3-stage ring, 1 sync per chunk. mma issue: 3 passes of 16
// independent accumulators (no same-acc back-to-back).
// ---------------------------------------------------------------------------
#define GSM (3 * 32768)

__global__ __launch_bounds__(256, 2) void gemm_fused(
    int mode, const float* __restrict__ bias, float* __restrict__ outF)
{
    extern __shared__ char smem[];
    const uint32_t sb = smem_u32(smem);
    const int tid = threadIdx.x;
    const int wid = tid >> 5;
    const int lane = tid & 31;
    const int wm = wid >> 2;
    const int wn = wid & 3;

    const bf16 *Ahi, *Alo, *Whi, *Wlo;
    bf16 *Ch = nullptr, *Cl = nullptr;
    float* Cf = nullptr;
    int my;
    if (mode) {
        Ahi = g_Ch; Alo = g_Cl; Whi = g_w_hi[3]; Wlo = g_w_lo[3];
        Cf = outF; my = blockIdx.y;
    } else {
        int y = blockIdx.y;
        if (y < 128)      { Ahi = g_qa_hi; Alo = g_qa_lo; Whi = g_w_hi[0]; Wlo = g_w_lo[0];
                            Ch = g_Qh; Cl = g_Ql; my = y; }
        else if (y < 384) { Ahi = g_ka_hi; Alo = g_ka_lo; Whi = g_w_hi[1]; Wlo = g_w_lo[1];
                            Ch = g_Kh; Cl = g_Kl; my = y - 128; }
        else              { Ahi = g_va_hi; Alo = g_va_lo; Whi = g_w_hi[2]; Wlo = g_w_lo[2];
                            Ch = g_Vh; Cl = g_Vl; my = y - 384; }
    }
    const int m0 = my * 128;
    const int n0 = blockIdx.x * 128;

    const int r = tid >> 1;
    const int half = tid & 1;
    uint32_t so[4];
#pragma unroll
    for (int i = 0; i < 4; i++) {
        uint32_t bo = (uint32_t)r * 128 + half * 64 + i * 16;
        so[i] = bo ^ ((bo >> 3) & 0x70);
    }
    const bf16* Asrc = half ? Alo : Ahi;
    const bf16* Wsrc = half ? Wlo : Whi;

    const int lrow = lane & 15;
    const uint32_t kxor = (uint32_t)(lane & 7) << 4;
    const uint32_t khalf = (uint32_t)(lane >> 4) * 16;

    float acc[4][4][4];
#pragma unroll
    for (int i = 0; i < 4; i++)
#pragma unroll
        for (int f = 0; f < 4; f++)
#pragma unroll
            for (int c = 0; c < 4; c++) acc[i][f][c] = 0.f;

    auto issue = [&](int kc, int buf) {
        const char* ag = (const char*)(Asrc + (size_t)(m0 + r) * 512 + kc * 32);
        const char* bg = (const char*)(Wsrc + (size_t)(n0 + r) * 512 + kc * 32);
        uint32_t ab = sb + (uint32_t)buf * 32768;
        uint32_t bb = ab + 16384;
#pragma unroll
        for (int i = 0; i < 4; i++) {
            cp16(ab + so[i], ag + i * 16);
            cp16(bb + so[i], bg + i * 16);
        }
        asm volatile("cp.async.commit_group;" ::: "memory");
    };

    issue(0, 0);
    issue(1, 1);

    for (int kc = 0; kc < 16; kc++) {
        if (kc == 15) asm volatile("cp.async.wait_group 0;" ::: "memory");
        else          asm volatile("cp.async.wait_group 1;" ::: "memory");
        __syncthreads();
        if (kc + 2 < 16) issue(kc + 2, (kc + 2) % 3);

        const uint32_t ab = sb + (uint32_t)(kc % 3) * 32768;
        const uint32_t bb = ab + 16384;
#pragma unroll
        for (int s = 0; s < 2; s++) {
            const uint32_t khi = ((uint32_t)(s * 32) + khalf) ^ kxor;
            const uint32_t klo = ((uint32_t)(64 + s * 32) + khalf) ^ kxor;
            uint32_t af[4][4], bh[2][4], bl[2][4];
#pragma unroll
            for (int im = 0; im < 4; im++)
                ldsm_x4(af[im][0], af[im][1], af[im][2], af[im][3],
                        ab + (uint32_t)(wm * 64 + im * 16 + lrow) * 128 + khi);
#pragma unroll
            for (int nb = 0; nb < 2; nb++) {
                uint32_t rowa = bb + (uint32_t)(wn * 32 + nb * 16 + lrow) * 128;
                ldsm_x4(bh[nb][0], bh[nb][1], bh[nb][2], bh[nb][3], rowa + khi);
                ldsm_x4(bl[nb][0], bl[nb][1], bl[nb][2], bl[nb][3], rowa + klo);
            }
            // pass 1: ah x Wh  (16 independent accumulators)
#pragma unroll
            for (int im = 0; im < 4; im++)
#pragma unroll
                for (int f = 0; f < 4; f++)
                    mma_bf16(acc[im][f], af[im],
                             bh[f >> 1][f & 1], bh[f >> 1][(f & 1) + 2]);
            // pass 2: ah x Wl
#pragma unroll
            for (int im = 0; im < 4; im++)
#pragma unroll
                for (int f = 0; f < 4; f++)
                    mma_bf16(acc[im][f], af[im],
                             bl[f >> 1][f & 1], bl[f >> 1][(f & 1) + 2]);
            // reload al, pass 3: al x Wh
#pragma unroll
            for (int im = 0; im < 4; im++)
                ldsm_x4(af[im][0], af[im][1], af[im][2], af[im][3],
                        ab + (uint32_t)(wm * 64 + im * 16 + lrow) * 128 + klo);
#pragma unroll
            for (int im = 0; im < 4; im++)
#pragma unroll
                for (int f = 0; f < 4; f++)
                    mma_bf16(acc[im][f], af[im],
                             bh[f >> 1][f & 1], bh[f >> 1][(f & 1) + 2]);
        }
    }

    const int crow = lane >> 2;
    const int ccol = (lane & 3) * 2;
#pragma unroll
    for (int im = 0; im < 4; im++) {
#pragma unroll
        for (int f = 0; f < 4; f++) {
            int row = m0 + wm * 64 + im * 16 + crow;
            int col = n0 + wn * 32 + (f >> 1) * 16 + (f & 1) * 8 + ccol;
            if (Cf) {
                float b0 = bias ? bias[col] : 0.f;
                float b1 = bias ? bias[col + 1] : 0.f;
                float2 v0 = {acc[im][f][0] + b0, acc[im][f][1] + b1};
                float2 v1 = {acc[im][f][2] + b0, acc[im][f][3] + b1};
                *(float2*)&Cf[(size_t)row * 512 + col] = v0;
                *(float2*)&Cf[(size_t)(row + 8) * 512 + col] = v1;
            } else {
                uint32_t hp, lp;
                split2(acc[im][f][0], acc[im][f][1], hp, lp);
                *(uint32_t*)&Ch[(size_t)row * 512 + col] = hp;
                *(uint32_t*)&Cl[(size_t)row * 512 + col] = lp;
                split2(acc[im][f][2], acc[im][f][3], hp, lp);
                *(uint32_t*)&Ch[(size_t)(row + 8) * 512 + col] = hp;
                *(uint32_t*)&Cl[(size_t)(row + 8) * 512 + col] = lp;
            }
        }
    }
}

// ---------------------------------------------------------------------------
// Tensor-core flash attention. CTA: 128 q-rows x one (b,h); 8 warps;
// S-tiles of 64; double-buffered KV + bitmask; interleaved mma issue
// (4 independent accumulators between same-acc reuses); 2 CTAs/SM.
// ---------------------------------------------------------------------------
#define ATT_BUF 33792                    // Kh 8K | Kl 8K | Vh 8K | Vl 8K | mask 1K
#define ATT_SM  (32768 + 2 * ATT_BUF)    // + Q hi/lo 32K  = 100352

__global__ __launch_bounds__(256, 2) void flash_tc()
{
    extern __shared__ char smem[];
    const uint32_t sb = smem_u32(smem);
    const int tid = threadIdx.x;
    const int wid = tid >> 5;
    const int lane = tid & 31;
    const int b = blockIdx.y >> 3;
    const int hd = blockIdx.y & 7;
    const int p0 = blockIdx.x * 128;

    const int lrow = lane & 15;
    const uint32_t kxor = (uint32_t)(lane & 7) << 4;
    const uint32_t khalf = (uint32_t)(lane >> 4) * 16;

    // ---- Q load (once; joins tile-0's commit group) ----
    const int qr = tid >> 1;
    const int qhalf = tid & 1;
    {
        const char* sq_h = (const char*)(g_Qh + (size_t)(b * PPN + p0 + qr) * 512 + hd * 64)
                           + qhalf * 64;
        const char* sq_l = (const char*)(g_Ql + (size_t)(b * PPN + p0 + qr) * 512 + hd * 64)
                           + qhalf * 64;
#pragma unroll
        for (int i = 0; i < 4; i++) {
            uint32_t bo = (uint32_t)qr * 128 + qhalf * 64 + i * 16;
            uint32_t sw = bo ^ ((bo >> 3) & 0x70);
            cp16(sb + sw, sq_h + i * 16);
            cp16(sb + 16384 + sw, sq_l + i * 16);
        }
    }

    // ---- K/V tile addressing ----
    const int kvr = tid >> 2;
    const int kvq = tid & 3;
    uint32_t kvsw0, kvsw1;
    {
        uint32_t bo0 = (uint32_t)kvr * 128 + kvq * 32;
        uint32_t bo1 = bo0 + 16;
        kvsw0 = bo0 ^ ((bo0 >> 3) & 0x70);
        kvsw1 = bo1 ^ ((bo1 >> 3) & 0x70);
    }

    auto issue_tile = [&](int t) {
        const uint32_t bufo = sb + 32768 + (uint32_t)(t & 1) * ATT_BUF;
        const int s0 = t * 64;
        const size_t kvrow = (size_t)(b * SSN + s0 + kvr) * 512 + hd * 64;
        const char* srcKh = (const char*)(g_Kh + kvrow) + kvq * 32;
        const char* srcKl = (const char*)(g_Kl + kvrow) + kvq * 32;
        const char* srcVh = (const char*)(g_Vh + kvrow) + kvq * 32;
        const char* srcVl = (const char*)(g_Vl + kvrow) + kvq * 32;
        cp16(bufo + kvsw0, srcKh);          cp16(bufo + kvsw1, srcKh + 16);
        cp16(bufo + 8192 + kvsw0, srcKl);   cp16(bufo + 8192 + kvsw1, srcKl + 16);
        cp16(bufo + 16384 + kvsw0, srcVh);  cp16(bufo + 16384 + kvsw1, srcVh + 16);
        cp16(bufo + 24576 + kvsw0, srcVl);  cp16(bufo + 24576 + kvsw1, srcVl + 16);
        if (tid < 128) {
            const unsigned char* srcM =
                g_mskb + (size_t)(b * PPN + p0 + tid) * (SSN / 8) + t * 8;
            cp8(bufo + 32768 + (uint32_t)tid * 8, srcM);
        }
        asm volatile("cp.async.commit_group;" ::: "memory");
    };

    issue_tile(0);

    float m0 = -1e30f, m1 = -1e30f, l0 = 0.f, l1 = 0.f;
    float oacc[8][4];
#pragma unroll
    for (int d = 0; d < 8; d++)
#pragma unroll
        for (int c = 0; c < 4; c++) oacc[d][c] = 0.f;

    const int r0 = lane >> 2;
    const int mcol = (lane & 3) * 2;

    for (int t = 0; t < 16; t++) {
        asm volatile("cp.async.wait_group 0;" ::: "memory");
        __syncthreads();
        if (t < 15) issue_tile(t + 1);

        const uint32_t bufo = sb + 32768 + (uint32_t)(t & 1) * ATT_BUF;
        const uint32_t Khb = bufo, Klb = bufo + 8192;
        const uint32_t Vhb = bufo + 16384, Vlb = bufo + 24576;
        const char* mskp = smem + (bufo - sb) + 32768;

        // ---- scores (ng pairs: 4 independent accumulators per pass) ----
        float sacc[8][4];
#pragma unroll
        for (int n = 0; n < 8; n++)
#pragma unroll
            for (int c = 0; c < 4; c++) sacc[n][c] = 0.f;

#pragma unroll
        for (int kc = 0; kc < 4; kc++) {
            const uint32_t kpart = ((uint32_t)(kc * 32) + khalf) ^ kxor;
            uint32_t ah[4], al[4];
            ldsm_x4(ah[0], ah[1], ah[2], ah[3],
                    sb + (uint32_t)(wid * 16 + lrow) * 128 + kpart);
            ldsm_x4(al[0], al[1], al[2], al[3],
                    sb + 16384 + (uint32_t)(wid * 16 + lrow) * 128 + kpart);
#pragma unroll
            for (int gp = 0; gp < 2; gp++) {
                uint32_t kh[2][4], kl[2][4];
#pragma unroll
                for (int g = 0; g < 2; g++) {
                    uint32_t rowa = (uint32_t)((gp * 2 + g) * 16 + lrow) * 128 + kpart;
                    ldsm_x4(kh[g][0], kh[g][1], kh[g][2], kh[g][3], Khb + rowa);
                    ldsm_x4(kl[g][0], kl[g][1], kl[g][2], kl[g][3], Klb + rowa);
                }
                float* s0p = sacc[4 * gp + 0];
                float* s1p = sacc[4 * gp + 1];
                float* s2p = sacc[4 * gp + 2];
                float* s3p = sacc[4 * gp + 3];
                mma_bf16(s0p, ah, kh[0][0], kh[0][2]);
                mma_bf16(s1p, ah, kh[0][1], kh[0][3]);
                mma_bf16(s2p, ah, kh[1][0], kh[1][2]);
                mma_bf16(s3p, ah, kh[1][1], kh[1][3]);
                mma_bf16(s0p, ah, kl[0][0], kl[0][2]);
                mma_bf16(s1p, ah, kl[0][1], kl[0][3]);
                mma_bf16(s2p, ah, kl[1][0], kl[1][2]);
                mma_bf16(s3p, ah, kl[1][1], kl[1][3]);
                mma_bf16(s0p, al, kh[0][0], kh[0][2]);
                mma_bf16(s1p, al, kh[0][1], kh[0][3]);
                mma_bf16(s2p, al, kh[1][0], kh[1][2]);
                mma_bf16(s3p, al, kh[1][1], kh[1][3]);
            }
        }

        // ---- bitmask + online softmax ----
        const float scale = 0.125f;
        const uint64_t mA = *(const uint64_t*)(mskp + (wid * 16 + r0) * 8);
        const uint64_t mB = *(const uint64_t*)(mskp + (wid * 16 + r0 + 8) * 8);
        float mx0 = -1e30f, mx1 = -1e30f;
#pragma unroll
        for (int nb = 0; nb < 8; nb++) {
            const int sh = nb * 8 + mcol;
            float* s = sacc[nb];
            s[0] = ((mA >> sh) & 1)       ? -1e30f : s[0] * scale;
            s[1] = ((mA >> (sh + 1)) & 1) ? -1e30f : s[1] * scale;
            s[2] = ((mB >> sh) & 1)       ? -1e30f : s[2] * scale;
            s[3] = ((mB >> (sh + 1)) & 1) ? -1e30f : s[3] * scale;
            mx0 = fmaxf(mx0, fmaxf(s[0], s[1]));
            mx1 = fmaxf(mx1, fmaxf(s[2], s[3]));
        }
        mx0 = fmaxf(mx0, __shfl_xor_sync(0xffffffffu, mx0, 1));
        mx0 = fmaxf(mx0, __shfl_xor_sync(0xffffffffu, mx0, 2));
        mx1 = fmaxf(mx1, __shfl_xor_sync(0xffffffffu, mx1, 1));
        mx1 = fmaxf(mx1, __shfl_xor_sync(0xffffffffu, mx1, 2));
        float mn0 = fmaxf(m0, mx0), mn1 = fmaxf(m1, mx1);
        float f0 = __expf(m0 - mn0), f1 = __expf(m1 - mn1);
        m0 = mn0; m1 = mn1;
        float sum0 = 0.f, sum1 = 0.f;
#pragma unroll
        for (int nb = 0; nb < 8; nb++) {
            float* s = sacc[nb];
            s[0] = __expf(s[0] - mn0); s[1] = __expf(s[1] - mn0);
            s[2] = __expf(s[2] - mn1); s[3] = __expf(s[3] - mn1);
            sum0 += s[0] + s[1];
            sum1 += s[2] + s[3];
        }
        sum0 += __shfl_xor_sync(0xffffffffu, sum0, 1);
        sum0 += __shfl_xor_sync(0xffffffffu, sum0, 2);
        sum1 += __shfl_xor_sync(0xffffffffu, sum1, 1);
        sum1 += __shfl_xor_sync(0xffffffffu, sum1, 2);
        l0 = f0 * l0 + sum0;
        l1 = f1 * l1 + sum1;
#pragma unroll
        for (int d = 0; d < 8; d++) {
            oacc[d][0] *= f0; oacc[d][1] *= f0;
            oacc[d][2] *= f1; oacc[d][3] *= f1;
        }

        // ---- P @ V (db pairs: 4 independent accumulators per pass) ----
#pragma unroll
        for (int kc = 0; kc < 4; kc++) {
            uint32_t ph[4], pl[4];
            float* pe = sacc[2 * kc];
            float* po = sacc[2 * kc + 1];
            split2(pe[0], pe[1], ph[0], pl[0]);
            split2(pe[2], pe[3], ph[1], pl[1]);
            split2(po[0], po[1], ph[2], pl[2]);
            split2(po[2], po[3], ph[3], pl[3]);
            const uint32_t srow = (uint32_t)(kc * 16 + lrow) * 128;
#pragma unroll
            for (int dp = 0; dp < 2; dp++) {
                uint32_t vh[2][4], vl[2][4];
#pragma unroll
                for (int g = 0; g < 2; g++) {
                    const uint32_t dpart = ((uint32_t)((dp * 2 + g) * 32) + khalf) ^ kxor;
                    ldsm_x4_t(vh[g][0], vh[g][1], vh[g][2], vh[g][3], Vhb + srow + dpart);
                    ldsm_x4_t(vl[g][0], vl[g][1], vl[g][2], vl[g][3], Vlb + srow + dpart);
                }
                float* o0p = oacc[4 * dp + 0];
                float* o1p = oacc[4 * dp + 1];
                float* o2p = oacc[4 * dp + 2];
                float* o3p = oacc[4 * dp + 3];
                mma_bf16(o0p, ph, vh[0][0], vh[0][1]);
                mma_bf16(o1p, ph, vh[0][2], vh[0][3]);
                mma_bf16(o2p, ph, vh[1][0], vh[1][1]);
                mma_bf16(o3p, ph, vh[1][2], vh[1][3]);
                mma_bf16(o0p, ph, vl[0][0], vl[0][1]);
                mma_bf16(o1p, ph, vl[0][2], vl[0][3]);
                mma_bf16(o2p, ph, vl[1][0], vl[1][1]);
                mma_bf16(o3p, ph, vl[1][2], vl[1][3]);
                mma_bf16(o0p, pl, vh[0][0], vh[0][1]);
                mma_bf16(o1p, pl, vh[0][2], vh[0][3]);
                mma_bf16(o2p, pl, vh[1][0], vh[1][1]);
                mma_bf16(o3p, pl, vh[1][2], vh[1][3]);
            }
        }
    }

    // ---- epilogue: normalize, split, store ctx ----
    const float inv0 = 1.f / l0;
    const float inv1 = 1.f / l1;
    const size_t rowA = (size_t)(b * PPN + p0 + wid * 16 + r0) * 512 + hd * 64;
    const size_t rowB = rowA + (size_t)8 * 512;
#pragma unroll
    for (int d = 0; d < 8; d++) {
        uint32_t hp, lp;
        split2(oacc[d][0] * inv0, oacc[d][1] * inv0, hp, lp);
        *(uint32_t*)&g_Ch[rowA + d * 8 + mcol] = hp;
        *(uint32_t*)&g_Cl[rowA + d * 8 + mcol] = lp;
        split2(oacc[d][2] * inv1, oacc[d][3] * inv1, hp, lp);
        *(uint32_t*)&g_Ch[rowB + d * 8 + mcol] = hp;
        *(uint32_t*)&g_Cl[rowB + d * 8 + mcol] = lp;
    }
}

// ---------------------------------------------------------------------------
extern "C" void kernel_launch(void* const* d_in, const int* in_sizes, int n_in,
                              void* d_out, int out_size)
{
    const float* query = (const float*)d_in[0];
    const float* key   = (const float*)d_in[1];
    const float* value = (const float*)d_in[2];
    const int*   mask  = (const int*)d_in[3];
    const float* W0 = (const float*)d_in[4];
    const float* W1 = (const float*)d_in[5];
    const float* W2 = (const float*)d_in[6];
    const float* W3 = (const float*)d_in[7];
    const float* bo = (const float*)d_in[8];
    float* out = (float*)d_out;

    bf16 *wh, *wl;
    unsigned int* mkb;
    cudaGetSymbolAddress((void**)&wh, g_w_hi);
    cudaGetSymbolAddress((void**)&wl, g_w_lo);
    cudaGetSymbolAddress((void**)&mkb, g_mskb);

    cudaFuncSetAttribute(gemm_fused, cudaFuncAttributeMaxDynamicSharedMemorySize, GSM);
    cudaFuncSetAttribute(flash_tc, cudaFuncAttributeMaxDynamicSharedMemorySize, ATT_SM);

    dim3 blk(256);

    // Launch order puts gemm_fused 4th (ncu captures the 4th launch).
    convert_qkv<<<(N4Q + 2 * N4K + 255) / 256, 256>>>(query, key, value);
    convert_split_w<<<dim3(EE * EE / 4 / 256, 4), 256>>>(
        W0, W1, W2, W3, wh, wl, EE * EE / 4);
    pack_mask_bits<<<(BBSZ * PPN * SSN / 32 + 255) / 256, 256>>>(
        mask, mkb, BBSZ * PPN * SSN / 32);

    gemm_fused<<<dim3(4, 640), blk, GSM>>>(0, nullptr, nullptr);

    flash_tc<<<dim3(PPN / 128, BBSZ * HH), blk, ATT_SM>>>();

    gemm_fused<<<dim3(4, 128), blk, GSM>>>(1, bo, out);
}